// round 7
// baseline (speedup 1.0000x reference)
#include <cuda_runtime.h>
#include <cstddef>
#include <cstdint>

#define N_NODES 50000
#define C_DIM   64
#define HID_DIM 128
#define R_DIM   16
#define B_DIM   2
#define L_DIM   12
#define E_EDGES 1600000
#define T_DIM   8
#define M_ROWS  (B_DIM * N_NODES)   // 100000

// Tables laid out [node][batch][16 floats]: one node = one 128B line.
__device__ __align__(128) float4 g_a[M_ROWS * 4];
__device__ __align__(128) float4 g_b[M_ROWS * 4];

__device__ __forceinline__ uint32_t f2tf(float x) {
    uint32_t r;
    asm("cvt.rna.tf32.f32 %0, %1;" : "=r"(r) : "f"(x));
    return r;
}

__device__ __forceinline__ void mma_tf32(float* d, uint32_t a0, uint32_t a1,
                                         uint32_t a2, uint32_t a3,
                                         uint32_t b0, uint32_t b1) {
    asm volatile(
        "mma.sync.aligned.m16n8k8.row.col.f32.tf32.tf32.f32 "
        "{%0,%1,%2,%3}, {%4,%5,%6,%7}, {%8,%9}, {%0,%1,%2,%3};"
        : "+f"(d[0]), "+f"(d[1]), "+f"(d[2]), "+f"(d[3])
        : "r"(a0), "r"(a1), "r"(a2), "r"(a3), "r"(b0), "r"(b1));
}

// k-permutation within each 16-k group: lane t's float4 at phys 4t..4t+3
// = logical k {t, t+4, t+8, t+12} (+ group*16).
__device__ __forceinline__ int kperm(int k) {
    return ((k >> 4) << 4) + 4 * (k & 3) + ((k >> 2) & 3);
}

// ---------------------------------------------------------------------------
// Kernel 1: tf32 tensor-core MLP. 128-row tile, 256 threads, one weight set
// per blockIdx.y. Strides: KS=80 for k=64 arrays, HS2=144 for k=128 arrays
// (both conflict-free for LDS.128 fragment loads). Hid aliases Hsm+Wsm.
// smem = 91,136 B -> 2 CTAs/SM.
// ---------------------------------------------------------------------------
#define KS  80
#define HS2 144

__global__ __launch_bounds__(256, 2)
void mlp_kernel(const float* __restrict__ X,
                const float* __restrict__ W1s, const float* __restrict__ b1s,
                const float* __restrict__ W2s, const float* __restrict__ b2s,
                const float* __restrict__ W1d, const float* __restrict__ b1d,
                const float* __restrict__ W2d, const float* __restrict__ b2d)
{
    extern __shared__ float sh[];
    float* W2sm = sh;                     // [16][HS2]   2304 floats
    float* Hsm  = sh + 16 * HS2;          // [128][KS]   10240 floats
    float* Wsm  = Hsm + 128 * KS;         // [128][KS]   10240 floats
    float* Hid  = Hsm;                    // [128][HS2]  18432 <= 20480 (alias)

    const int tid  = threadIdx.x;
    const int lane = tid & 31;
    const int warp = tid >> 5;
    const int g    = lane >> 2;   // 0..7
    const int t    = lane & 3;    // 0..3
    const int m0   = blockIdx.x * 128;
    const int set  = blockIdx.y;

    const float* W1 = set ? W1d : W1s;
    const float* b1 = set ? b1d : b1s;
    const float* W2 = set ? W2d : W2s;
    const float* b2 = set ? b2d : b2s;
    float4* outTab  = set ? g_b : g_a;

    uint32_t* Hu  = (uint32_t*)Hsm;
    uint32_t* Wu  = (uint32_t*)Wsm;
    uint32_t* Du  = (uint32_t*)Hid;
    uint32_t* W2u = (uint32_t*)W2sm;

    // ---- Stage H tile (tf32 bits, permuted k), stride KS ----
    #pragma unroll
    for (int u = 0; u < 8; u++) {
        int id = tid + 256 * u;            // 2048 float4: 128 rows x 16 quads
        int r  = id >> 4, cg = id & 15;
        int m  = m0 + r;
        float4 v = make_float4(0.f, 0.f, 0.f, 0.f);
        if (m < M_ROWS) {
            int b = m / N_NODES;
            int n = m - b * N_NODES;
            v = *(const float4*)&X[(((size_t)b * T_DIM + (T_DIM - 1)) * N_NODES + n) * C_DIM + cg * 4];
        }
        int base = r * KS + ((cg >> 2) << 4) + (cg & 3);
        Hu[base +  0] = f2tf(v.x);
        Hu[base +  4] = f2tf(v.y);
        Hu[base +  8] = f2tf(v.z);
        Hu[base + 12] = f2tf(v.w);
    }
    // ---- Stage W1 transposed [n][perm k], stride KS ----
    #pragma unroll
    for (int u = 0; u < 8; u++) {
        int id = tid + 256 * u;            // 2048 float4 of W1 [64][128]
        int k = id >> 5, ng = id & 31;
        float4 v = *(const float4*)&W1[k * 128 + ng * 4];
        int kb = kperm(k);
        Wu[(ng * 4 + 0) * KS + kb] = f2tf(v.x);
        Wu[(ng * 4 + 1) * KS + kb] = f2tf(v.y);
        Wu[(ng * 4 + 2) * KS + kb] = f2tf(v.z);
        Wu[(ng * 4 + 3) * KS + kb] = f2tf(v.w);
    }
    // ---- Stage W2 transposed [r][perm k], stride HS2 ----
    #pragma unroll
    for (int u = 0; u < 2; u++) {
        int id = tid + 256 * u;            // 512 float4 of W2 [128][16]
        int k = id >> 2, rg = id & 3;
        float4 v = *(const float4*)&W2[k * 16 + rg * 4];
        int kb = kperm(k);
        W2u[(rg * 4 + 0) * HS2 + kb] = f2tf(v.x);
        W2u[(rg * 4 + 1) * HS2 + kb] = f2tf(v.y);
        W2u[(rg * 4 + 2) * HS2 + kb] = f2tf(v.z);
        W2u[(rg * 4 + 3) * HS2 + kb] = f2tf(v.w);
    }
    __syncthreads();

    // -------- Layer 1: M128 N128 K64 --------
    const int mr = warp >> 1;     // 0..3
    const int nc = warp & 1;      // 0..1
    float acc[2][8][4];
    #pragma unroll
    for (int mt = 0; mt < 2; mt++)
        #pragma unroll
        for (int nt = 0; nt < 8; nt++)
            #pragma unroll
            for (int i = 0; i < 4; i++) acc[mt][nt][i] = 0.0f;

    #pragma unroll
    for (int ks2 = 0; ks2 < 4; ks2++) {
        uint4 A0[2], A1[2];
        #pragma unroll
        for (int mt = 0; mt < 2; mt++) {
            int row = mr * 32 + mt * 16;
            A0[mt] = *(const uint4*)&Hu[(row + g)     * KS + ks2 * 16 + 4 * t];
            A1[mt] = *(const uint4*)&Hu[(row + g + 8) * KS + ks2 * 16 + 4 * t];
        }
        #pragma unroll
        for (int nt = 0; nt < 8; nt++) {
            int n = nc * 64 + nt * 8 + g;
            uint4 B = *(const uint4*)&Wu[n * KS + ks2 * 16 + 4 * t];
            #pragma unroll
            for (int mt = 0; mt < 2; mt++) {
                mma_tf32(acc[mt][nt], A0[mt].x, A1[mt].x, A0[mt].y, A1[mt].y, B.x, B.y);
                mma_tf32(acc[mt][nt], A0[mt].z, A1[mt].z, A0[mt].w, A1[mt].w, B.z, B.w);
            }
        }
    }
    __syncthreads();   // everyone done reading Hsm/Wsm before Hid overwrite

    // bias + relu -> Hid (stride HS2, permuted k)
    #pragma unroll
    for (int nt = 0; nt < 8; nt++) {
        int k0 = nc * 64 + nt * 8 + t * 2;
        float2 bb = __ldg((const float2*)&b1[k0]);
        int kb0 = kperm(k0), kb1 = kperm(k0 + 1);
        #pragma unroll
        for (int mt = 0; mt < 2; mt++) {
            int row = mr * 32 + mt * 16;
            float v0 = acc[mt][nt][0] + bb.x; v0 = v0 > 0.f ? v0 : 0.f;
            float v1 = acc[mt][nt][1] + bb.y; v1 = v1 > 0.f ? v1 : 0.f;
            float v2 = acc[mt][nt][2] + bb.x; v2 = v2 > 0.f ? v2 : 0.f;
            float v3 = acc[mt][nt][3] + bb.y; v3 = v3 > 0.f ? v3 : 0.f;
            Du[(row + g)     * HS2 + kb0] = f2tf(v0);
            Du[(row + g)     * HS2 + kb1] = f2tf(v1);
            Du[(row + g + 8) * HS2 + kb0] = f2tf(v2);
            Du[(row + g + 8) * HS2 + kb1] = f2tf(v3);
        }
    }
    __syncthreads();

    // -------- Layer 2: M128 N16 K128 --------
    {
        float acc2[2][4];
        #pragma unroll
        for (int nt = 0; nt < 2; nt++)
            #pragma unroll
            for (int i = 0; i < 4; i++) acc2[nt][i] = 0.0f;

        const int rowb = warp * 16;
        #pragma unroll
        for (int ks2 = 0; ks2 < 8; ks2++) {
            uint4 A0 = *(const uint4*)&Du[(rowb + g)     * HS2 + ks2 * 16 + 4 * t];
            uint4 A1 = *(const uint4*)&Du[(rowb + g + 8) * HS2 + ks2 * 16 + 4 * t];
            #pragma unroll
            for (int nt = 0; nt < 2; nt++) {
                uint4 B = *(const uint4*)&W2u[(nt * 8 + g) * HS2 + ks2 * 16 + 4 * t];
                mma_tf32(acc2[nt], A0.x, A1.x, A0.y, A1.y, B.x, B.y);
                mma_tf32(acc2[nt], A0.z, A1.z, A0.w, A1.w, B.z, B.w);
            }
        }

        // epilogue: +b2, write tables in [node][batch][16] layout
        #pragma unroll
        for (int nt = 0; nt < 2; nt++) {
            int r0 = nt * 8 + t * 2;
            float2 bb = __ldg((const float2*)&b2[r0]);
            int m = m0 + rowb + g;
            if (m < M_ROWS) {
                int b = m / N_NODES, n = m - b * N_NODES;
                float2 v; v.x = acc2[nt][0] + bb.x; v.y = acc2[nt][1] + bb.y;
                *(float2*)((float*)outTab + ((size_t)n * 2 + b) * 16 + r0) = v;
            }
            m = m0 + rowb + g + 8;
            if (m < M_ROWS) {
                int b = m / N_NODES, n = m - b * N_NODES;
                float2 v; v.x = acc2[nt][2] + bb.x; v.y = acc2[nt][3] + bb.y;
                *(float2*)((float*)outTab + ((size_t)n * 2 + b) * 16 + r0) = v;
            }
        }
    }
}

// ---------------------------------------------------------------------------
// Kernel 2: edge scoring. 256 edges/block, 256 threads.
// Gather: warp instr = 2 edges x one table = 4 fully-consumed 128B lines.
// Compute: thread = edge, both batches; coalesced STG.32 stores.
// ---------------------------------------------------------------------------
#define EPB 256
#define RAW_STRIDE 17

__global__ __launch_bounds__(256)
void edge_kernel(const int* __restrict__ eidx,
                 const float* __restrict__ gamma,
                 float* __restrict__ out)
{
    extern __shared__ float esh[];
    float4* raw = (float4*)esh;                        // [EPB][17]
    int*    sIJ = (int*)(esh + EPB * RAW_STRIDE * 4);  // [2][EPB]
    float*  g   = (float*)(sIJ + 2 * EPB);             // [12][16]

    const int tid = threadIdx.x;
    const long long e0 = (long long)blockIdx.x * EPB;

    sIJ[tid]       = eidx[e0 + tid];
    sIJ[tid + EPB] = eidx[(size_t)E_EDGES + e0 + tid];
    if (tid < L_DIM * R_DIM) g[tid] = gamma[tid];
    __syncthreads();

    // Gather: 4096 float4, 16/thread in 2 rounds of 8.
    #pragma unroll
    for (int rnd = 0; rnd < 2; rnd++) {
        float4 regs[8];
        int    dsts[8];
        #pragma unroll
        for (int u = 0; u < 8; u++) {
            int gid  = tid + 256 * (rnd * 8 + u);
            int edge = gid >> 4;
            int sub  = gid & 15;
            int tab  = sub >> 3;
            int k    = sub & 7;
            int node = sIJ[tab * EPB + edge];
            const float4* tbl = tab ? g_b : g_a;
            regs[u] = tbl[(size_t)node * 8 + k];
            dsts[u] = edge * RAW_STRIDE + sub;
        }
        #pragma unroll
        for (int u = 0; u < 8; u++) raw[dsts[u]] = regs[u];
    }
    __syncthreads();

    // Compute: thread = edge tid, both batches.
    const float4* base = raw + tid * RAW_STRIDE;
    #pragma unroll
    for (int bb = 0; bb < 2; bb++) {
        float p[16];
        #pragma unroll
        for (int q = 0; q < 4; q++) {
            float4 av = base[bb * 4 + q];
            float4 bv = base[8 + bb * 4 + q];
            p[q * 4 + 0] = av.x * bv.x;
            p[q * 4 + 1] = av.y * bv.y;
            p[q * 4 + 2] = av.z * bv.z;
            p[q * 4 + 3] = av.w * bv.w;
        }
        float* o = out + (size_t)bb * L_DIM * E_EDGES + e0 + tid;
        #pragma unroll
        for (int l = 0; l < L_DIM; l++) {
            float s = 0.0f;
            #pragma unroll
            for (int r = 0; r < R_DIM; r++) s += g[l * R_DIM + r] * p[r];
            o[(size_t)l * E_EDGES] = s;
        }
    }
}

// ---------------------------------------------------------------------------
// Launch
// ---------------------------------------------------------------------------
extern "C" void kernel_launch(void* const* d_in, const int* in_sizes, int n_in,
                              void* d_out, int out_size)
{
    const float* X    = (const float*)d_in[0];
    const int*   eidx = (const int*)d_in[1];
    const float* W1s  = (const float*)d_in[2];
    const float* b1s  = (const float*)d_in[3];
    const float* W2s  = (const float*)d_in[4];
    const float* b2s  = (const float*)d_in[5];
    const float* W1d  = (const float*)d_in[6];
    const float* b1d  = (const float*)d_in[7];
    const float* W2d  = (const float*)d_in[8];
    const float* b2d  = (const float*)d_in[9];
    const float* gamma= (const float*)d_in[10];
    float* out = (float*)d_out;

    const int mlp_smem  = (16 * HS2 + 128 * KS * 2) * (int)sizeof(float);     // 91,136 B
    const int edge_smem = EPB * RAW_STRIDE * 16 + 2 * EPB * (int)sizeof(int)
                          + L_DIM * R_DIM * (int)sizeof(float);                // ~72.5 KB
    static bool attr_done = false;
    if (!attr_done) {
        cudaFuncSetAttribute(mlp_kernel,  cudaFuncAttributeMaxDynamicSharedMemorySize, mlp_smem);
        cudaFuncSetAttribute(edge_kernel, cudaFuncAttributeMaxDynamicSharedMemorySize, edge_smem);
        attr_done = true;
    }

    dim3 grid1((M_ROWS + 127) / 128, 2, 1);
    mlp_kernel<<<grid1, 256, mlp_smem>>>(X, W1s, b1s, W2s, b2s, W1d, b1d, W2d, b2d);

    const int blocks2 = E_EDGES / EPB;
    edge_kernel<<<blocks2, 256, edge_smem>>>(eidx, gamma, out);
}

// round 8
// speedup vs baseline: 1.3763x; 1.3763x over previous
#include <cuda_runtime.h>
#include <cstddef>
#include <cstdint>

#define N_NODES 50000
#define C_DIM   64
#define HID_DIM 128
#define R_DIM   16
#define B_DIM   2
#define L_DIM   12
#define E_EDGES 1600000
#define T_DIM   8
#define M_ROWS  (B_DIM * N_NODES)   // 100000

// Tables laid out [node][batch][16 floats]: one node = one 128B line.
__device__ __align__(128) float4 g_a[M_ROWS * 4];
__device__ __align__(128) float4 g_b[M_ROWS * 4];

__device__ __forceinline__ uint32_t f2tf(float x) {
    uint32_t r;
    asm("cvt.rna.tf32.f32 %0, %1;" : "=r"(r) : "f"(x));
    return r;
}

__device__ __forceinline__ void mma_tf32(float* d, uint32_t a0, uint32_t a1,
                                         uint32_t a2, uint32_t a3,
                                         uint32_t b0, uint32_t b1) {
    asm volatile(
        "mma.sync.aligned.m16n8k8.row.col.f32.tf32.tf32.f32 "
        "{%0,%1,%2,%3}, {%4,%5,%6,%7}, {%8,%9}, {%0,%1,%2,%3};"
        : "+f"(d[0]), "+f"(d[1]), "+f"(d[2]), "+f"(d[3])
        : "r"(a0), "r"(a1), "r"(a2), "r"(a3), "r"(b0), "r"(b1));
}

// ---------------------------------------------------------------------------
// Kernel 1: tf32 tensor-core MLP. 128-row tile, 256 threads (8 warps),
// both weight sets looped in one block. All smem tiles ROW-MAJOR with pads
// chosen so staging STS is coalesced and fragment LDS.32 are conflict-free:
//   Hsm [128][68]  (68  % 32 = 4 -> A bank 4g+t, distinct)
//   W1sm[64][136]  (136 % 32 = 8 -> B bank 8t+g, distinct)
//   Hid [128][132] (132 % 32 = 4 -> A bank 4g+t, distinct)
//   W2sm[128][20]  (small; <=2-way on B loads)
// Hid aliases Hsm+W1sm. smem = 79,872 B -> 2 CTAs/SM.
// ---------------------------------------------------------------------------
#define SH  68
#define SW1 136
#define SHD 132
#define SW2 20

__global__ __launch_bounds__(256, 2)
void mlp_kernel(const float* __restrict__ X,
                const float* __restrict__ W1s, const float* __restrict__ b1s,
                const float* __restrict__ W2s, const float* __restrict__ b2s,
                const float* __restrict__ W1d, const float* __restrict__ b1d,
                const float* __restrict__ W2d, const float* __restrict__ b2d)
{
    extern __shared__ float sh[];
    float* W2sm = sh;                     // [128][20]  2560 fl
    float* Hsm  = sh + 128 * SW2;         // [128][68]  8704 fl
    float* W1sm = Hsm + 128 * SH;         // [64][136]  8704 fl
    float* Hid  = Hsm;                    // [128][132] 16896 <= 17408 (alias)

    const int tid  = threadIdx.x;
    const int lane = tid & 31;
    const int warp = tid >> 5;
    const int g    = lane >> 2;   // 0..7
    const int t    = lane & 3;    // 0..3
    const int m0   = blockIdx.x * 128;

    uint32_t* Hu  = (uint32_t*)Hsm;
    uint32_t* W1u = (uint32_t*)W1sm;
    uint32_t* W2u = (uint32_t*)W2sm;
    uint32_t* Du  = (uint32_t*)Hid;

    for (int set = 0; set < 2; set++) {
        const float* W1 = set ? W1d : W1s;
        const float* b1 = set ? b1d : b1s;
        const float* W2 = set ? W2d : W2s;
        const float* b2 = set ? b2d : b2s;
        float4* outTab  = set ? g_b : g_a;

        // ---- Stage H row-major [r][k] (coalesced STS.128) ----
        #pragma unroll
        for (int u = 0; u < 8; u++) {
            int id = tid + 256 * u;            // 2048 f4: 128 rows x 16 quads
            int r  = id >> 4, cg = id & 15;
            int m  = m0 + r;
            float4 v = make_float4(0.f, 0.f, 0.f, 0.f);
            if (m < M_ROWS) {
                int b = m / N_NODES;
                int n = m - b * N_NODES;
                v = *(const float4*)&X[(((size_t)b * T_DIM + (T_DIM - 1)) * N_NODES + n) * C_DIM + cg * 4];
            }
            uint4 w; w.x = f2tf(v.x); w.y = f2tf(v.y); w.z = f2tf(v.z); w.w = f2tf(v.w);
            *(uint4*)&Hu[r * SH + cg * 4] = w;
        }
        // ---- Stage W1 row-major [k][n] (coalesced) ----
        #pragma unroll
        for (int u = 0; u < 8; u++) {
            int id = tid + 256 * u;            // 2048 f4 of W1 [64][128]
            int k = id >> 5, ng = id & 31;
            float4 v = *(const float4*)&W1[k * 128 + ng * 4];
            uint4 w; w.x = f2tf(v.x); w.y = f2tf(v.y); w.z = f2tf(v.z); w.w = f2tf(v.w);
            *(uint4*)&W1u[k * SW1 + ng * 4] = w;
        }
        // ---- Stage W2 row-major [k][r] ----
        #pragma unroll
        for (int u = 0; u < 2; u++) {
            int id = tid + 256 * u;            // 512 f4 of W2 [128][16]
            int k = id >> 2, rg = id & 3;
            float4 v = *(const float4*)&W2[k * 16 + rg * 4];
            uint4 w; w.x = f2tf(v.x); w.y = f2tf(v.y); w.z = f2tf(v.z); w.w = f2tf(v.w);
            *(uint4*)&W2u[k * SW2 + rg * 4] = w;
        }
        __syncthreads();

        // -------- Layer 1: M128 N128 K64 --------
        const int mr = warp >> 1;     // 0..3: 32-row block
        const int nc = warp & 1;      // 0..1: 64-col block
        float acc[2][8][4];
        #pragma unroll
        for (int mt = 0; mt < 2; mt++)
            #pragma unroll
            for (int nt = 0; nt < 8; nt++)
                #pragma unroll
                for (int i = 0; i < 4; i++) acc[mt][nt][i] = 0.0f;

        #pragma unroll
        for (int kk = 0; kk < 8; kk++) {
            const int k0 = kk * 8;
            uint32_t a[2][4];
            #pragma unroll
            for (int mt = 0; mt < 2; mt++) {
                int row = mr * 32 + mt * 16;
                a[mt][0] = Hu[(row + g)     * SH + k0 + t];
                a[mt][1] = Hu[(row + g + 8) * SH + k0 + t];
                a[mt][2] = Hu[(row + g)     * SH + k0 + t + 4];
                a[mt][3] = Hu[(row + g + 8) * SH + k0 + t + 4];
            }
            #pragma unroll
            for (int nt = 0; nt < 8; nt++) {
                int n = nc * 64 + nt * 8 + g;
                uint32_t b0 = W1u[(k0 + t)     * SW1 + n];
                uint32_t b1v = W1u[(k0 + t + 4) * SW1 + n];
                mma_tf32(acc[0][nt], a[0][0], a[0][1], a[0][2], a[0][3], b0, b1v);
                mma_tf32(acc[1][nt], a[1][0], a[1][1], a[1][2], a[1][3], b0, b1v);
            }
        }
        __syncthreads();   // Hsm/W1sm dead -> Hid may overwrite

        // bias + relu -> Hid [row][k] (2-way STS.64 worst case)
        #pragma unroll
        for (int nt = 0; nt < 8; nt++) {
            int ncol = nc * 64 + nt * 8 + t * 2;
            float2 bb = __ldg((const float2*)&b1[ncol]);
            #pragma unroll
            for (int mt = 0; mt < 2; mt++) {
                int row = mr * 32 + mt * 16;
                float v0 = acc[mt][nt][0] + bb.x; v0 = v0 > 0.f ? v0 : 0.f;
                float v1 = acc[mt][nt][1] + bb.y; v1 = v1 > 0.f ? v1 : 0.f;
                float v2 = acc[mt][nt][2] + bb.x; v2 = v2 > 0.f ? v2 : 0.f;
                float v3 = acc[mt][nt][3] + bb.y; v3 = v3 > 0.f ? v3 : 0.f;
                uint2 w01; w01.x = f2tf(v0); w01.y = f2tf(v1);
                uint2 w23; w23.x = f2tf(v2); w23.y = f2tf(v3);
                *(uint2*)&Du[(row + g)     * SHD + ncol] = w01;
                *(uint2*)&Du[(row + g + 8) * SHD + ncol] = w23;
            }
        }
        __syncthreads();

        // -------- Layer 2: M128 N16 K128 --------
        {
            float acc2[2][4];
            #pragma unroll
            for (int nt = 0; nt < 2; nt++)
                #pragma unroll
                for (int i = 0; i < 4; i++) acc2[nt][i] = 0.0f;

            const int rowb = warp * 16;
            #pragma unroll
            for (int kk = 0; kk < 16; kk++) {
                const int k0 = kk * 8;
                uint32_t a0 = Du[(rowb + g)     * SHD + k0 + t];
                uint32_t a1 = Du[(rowb + g + 8) * SHD + k0 + t];
                uint32_t a2 = Du[(rowb + g)     * SHD + k0 + t + 4];
                uint32_t a3 = Du[(rowb + g + 8) * SHD + k0 + t + 4];
                #pragma unroll
                for (int nt = 0; nt < 2; nt++) {
                    uint32_t b0 = W2u[(k0 + t)     * SW2 + nt * 8 + g];
                    uint32_t b1v = W2u[(k0 + t + 4) * SW2 + nt * 8 + g];
                    mma_tf32(acc2[nt], a0, a1, a2, a3, b0, b1v);
                }
            }

            // epilogue: +b2, write tables in [node][batch][16] layout
            #pragma unroll
            for (int nt = 0; nt < 2; nt++) {
                int r0 = nt * 8 + t * 2;
                float2 bb = __ldg((const float2*)&b2[r0]);
                int m = m0 + rowb + g;
                if (m < M_ROWS) {
                    int b = m / N_NODES, n = m - b * N_NODES;
                    float2 v; v.x = acc2[nt][0] + bb.x; v.y = acc2[nt][1] + bb.y;
                    *(float2*)((float*)outTab + ((size_t)n * 2 + b) * 16 + r0) = v;
                }
                m = m0 + rowb + g + 8;
                if (m < M_ROWS) {
                    int b = m / N_NODES, n = m - b * N_NODES;
                    float2 v; v.x = acc2[nt][2] + bb.x; v.y = acc2[nt][3] + bb.y;
                    *(float2*)((float*)outTab + ((size_t)n * 2 + b) * 16 + r0) = v;
                }
            }
        }
        __syncthreads();   // Hid dead before next set re-stages Hsm/W1sm
    }
}

// ---------------------------------------------------------------------------
// Kernel 2: edge scoring (unchanged from measured 79us version).
// 256 edges/block, 256 threads. Gather -> smem stage -> per-edge compute.
// ---------------------------------------------------------------------------
#define EPB 256
#define RAW_STRIDE 17

__global__ __launch_bounds__(256)
void edge_kernel(const int* __restrict__ eidx,
                 const float* __restrict__ gamma,
                 float* __restrict__ out)
{
    extern __shared__ float esh[];
    float4* raw = (float4*)esh;                        // [EPB][17]
    int*    sIJ = (int*)(esh + EPB * RAW_STRIDE * 4);  // [2][EPB]
    float*  g   = (float*)(sIJ + 2 * EPB);             // [12][16]

    const int tid = threadIdx.x;
    const long long e0 = (long long)blockIdx.x * EPB;

    sIJ[tid]       = eidx[e0 + tid];
    sIJ[tid + EPB] = eidx[(size_t)E_EDGES + e0 + tid];
    if (tid < L_DIM * R_DIM) g[tid] = gamma[tid];
    __syncthreads();

    // Gather: 4096 float4, 16/thread in 2 rounds of 8.
    #pragma unroll
    for (int rnd = 0; rnd < 2; rnd++) {
        float4 regs[8];
        int    dsts[8];
        #pragma unroll
        for (int u = 0; u < 8; u++) {
            int gid  = tid + 256 * (rnd * 8 + u);
            int edge = gid >> 4;
            int sub  = gid & 15;
            int tab  = sub >> 3;
            int k    = sub & 7;
            int node = sIJ[tab * EPB + edge];
            const float4* tbl = tab ? g_b : g_a;
            regs[u] = tbl[(size_t)node * 8 + k];
            dsts[u] = edge * RAW_STRIDE + sub;
        }
        #pragma unroll
        for (int u = 0; u < 8; u++) raw[dsts[u]] = regs[u];
    }
    __syncthreads();

    // Compute: thread = edge tid, both batches.
    const float4* base = raw + tid * RAW_STRIDE;
    #pragma unroll
    for (int bb = 0; bb < 2; bb++) {
        float p[16];
        #pragma unroll
        for (int q = 0; q < 4; q++) {
            float4 av = base[bb * 4 + q];
            float4 bv = base[8 + bb * 4 + q];
            p[q * 4 + 0] = av.x * bv.x;
            p[q * 4 + 1] = av.y * bv.y;
            p[q * 4 + 2] = av.z * bv.z;
            p[q * 4 + 3] = av.w * bv.w;
        }
        float* o = out + (size_t)bb * L_DIM * E_EDGES + e0 + tid;
        #pragma unroll
        for (int l = 0; l < L_DIM; l++) {
            float s = 0.0f;
            #pragma unroll
            for (int r = 0; r < R_DIM; r++) s += g[l * R_DIM + r] * p[r];
            o[(size_t)l * E_EDGES] = s;
        }
    }
}

// ---------------------------------------------------------------------------
// Launch
// ---------------------------------------------------------------------------
extern "C" void kernel_launch(void* const* d_in, const int* in_sizes, int n_in,
                              void* d_out, int out_size)
{
    const float* X    = (const float*)d_in[0];
    const int*   eidx = (const int*)d_in[1];
    const float* W1s  = (const float*)d_in[2];
    const float* b1s  = (const float*)d_in[3];
    const float* W2s  = (const float*)d_in[4];
    const float* b2s  = (const float*)d_in[5];
    const float* W1d  = (const float*)d_in[6];
    const float* b1d  = (const float*)d_in[7];
    const float* W2d  = (const float*)d_in[8];
    const float* b2d  = (const float*)d_in[9];
    const float* gamma= (const float*)d_in[10];
    float* out = (float*)d_out;

    const int mlp_smem  = (128 * SW2 + 128 * SH + 64 * SW1) * (int)sizeof(float);  // 79,872 B
    const int edge_smem = EPB * RAW_STRIDE * 16 + 2 * EPB * (int)sizeof(int)
                          + L_DIM * R_DIM * (int)sizeof(float);
    static bool attr_done = false;
    if (!attr_done) {
        cudaFuncSetAttribute(mlp_kernel,  cudaFuncAttributeMaxDynamicSharedMemorySize, mlp_smem);
        cudaFuncSetAttribute(edge_kernel, cudaFuncAttributeMaxDynamicSharedMemorySize, edge_smem);
        attr_done = true;
    }

    const int blocks1 = (M_ROWS + 127) / 128;
    mlp_kernel<<<blocks1, 256, mlp_smem>>>(X, W1s, b1s, W2s, b2s, W1d, b1d, W2d, b2d);

    const int blocks2 = E_EDGES / EPB;
    edge_kernel<<<blocks2, 256, edge_smem>>>(eidx, gamma, out);
}